// round 10
// baseline (speedup 1.0000x reference)
#include <cuda_runtime.h>
#include <cstdint>
#include <cstddef>

#define BB 2
#define TT 2048
#define DD 1024
#define HH 16
#define HS 64
#define BT (BB*TT)

// Scratch (allocation-free rule: __device__ globals)
__device__ float g_q[BB*HH*TT*HS];   // hs-dim pair-permuted
__device__ float g_k[BB*HH*TT*HS];   // hs-dim pair-permuted
__device__ float g_v[BB*HH*TT*HS];   // hs-dim pair-permuted
__device__ float g_y[BT*DD];         // D-dim pair-permuted (falls out of permuted v)
__device__ float g_xc[BT*DD];        // tf32-rounded x, D-dim pair-permuted
__device__ float g_wc[4*DD*DD];      // tf32-rounded Wq,Wk,Wv,Wo, K-dim pair-permuted

__device__ __forceinline__ uint32_t f2tf(float x){
    uint32_t r; asm("cvt.rna.tf32.f32 %0, %1;" : "=r"(r) : "f"(x)); return r;
}
__device__ __forceinline__ float f2tff(float x){ return __uint_as_float(f2tf(x)); }

// pair-permutation within an 8-group: g -> 2*(g&3) + (g>>2)
__device__ __forceinline__ int p8(int n){
    int g = n & 7; return (n & ~7) | (((g & 3) << 1) | (g >> 2));
}

__device__ __forceinline__ void mma8(float* c, const uint32_t* a, const uint32_t* b){
    asm volatile(
        "mma.sync.aligned.m16n8k8.row.col.f32.tf32.tf32.f32 "
        "{%0,%1,%2,%3}, {%4,%5,%6,%7}, {%8,%9}, {%0,%1,%2,%3};\n"
        : "+f"(c[0]), "+f"(c[1]), "+f"(c[2]), "+f"(c[3])
        : "r"(a[0]), "r"(a[1]), "r"(a[2]), "r"(a[3]), "r"(b[0]), "r"(b[1]));
}

__device__ __forceinline__ void cpa16(float* dst_smem, const float* src){
    uint32_t d = (uint32_t)__cvta_generic_to_shared(dst_smem);
    asm volatile("cp.async.cg.shared.global [%0], [%1], 16;\n" :: "r"(d), "l"(src));
}
#define CPA_COMMIT() asm volatile("cp.async.commit_group;\n" ::: "memory")
#define CPA_WAIT0()  asm volatile("cp.async.wait_group 0;\n" ::: "memory")

// ---------------------------------------------------------------------------
// conv: tf32-round + K-dim pair-permute x and the 4 weights.
// grid (1024, 5), 256 thr.  Permutation is applied identically to both MMA
// operands of every GEMM, so results are k-sum-reorder equivalent only.
// ---------------------------------------------------------------------------
extern "C" __global__ void __launch_bounds__(256)
conv_kernel(const float* __restrict__ x,  const float* __restrict__ Wq,
            const float* __restrict__ Wk, const float* __restrict__ Wv,
            const float* __restrict__ Wo)
{
    const float4* src; float* dst; int n4;
    switch (blockIdx.y){
        case 0:  src = (const float4*)x;  dst = g_xc;            n4 = BT*DD/4; break;
        case 1:  src = (const float4*)Wq; dst = g_wc;            n4 = DD*DD/4; break;
        case 2:  src = (const float4*)Wk; dst = g_wc + DD*DD;    n4 = DD*DD/4; break;
        case 3:  src = (const float4*)Wv; dst = g_wc + 2*DD*DD;  n4 = DD*DD/4; break;
        default: src = (const float4*)Wo; dst = g_wc + 3*DD*DD;  n4 = DD*DD/4; break;
    }
    for (int i = blockIdx.x*blockDim.x + threadIdx.x; i < n4; i += gridDim.x*blockDim.x){
        float4 v = src[i];
        const int e0 = i * 4;                 // natural flat index of v.x
        float* d = dst + (e0 & ~7);           // 8-group base
        const int o = (e0 & 4) ? 1 : 0;       // g in {0..3} -> even slots, {4..7} -> odd
        d[o]     = f2tff(v.x);
        d[o + 2] = f2tff(v.y);
        d[o + 4] = f2tff(v.z);
        d[o + 6] = f2tff(v.w);
    }
}

// ---------------------------------------------------------------------------
// 128x128 tile of A(MxK row-major) * W^T (W is NxK row-major), K = DD = 1024.
// Inputs pre-rounded to tf32 and K-pair-permuted in gmem -> no CVT in loop,
// fragment loads are LDS.64. cp.async double-buffered, k-chunk 32.
// 256 threads, 8 warps; warp tile 64x32.
// ---------------------------------------------------------------------------
__device__ __forceinline__ void gemm_128_128(
    const float* __restrict__ A, const float* __restrict__ W,
    int m0, int n0, float acc[16][4], float* sm)
{
    float* sAb[2] = { sm,          sm + 4608 };
    float* sBb[2] = { sm + 9216,   sm + 13824 };

    const int t = threadIdx.x, lane = t & 31, warp = t >> 5;
    const int wm = (warp >> 2) * 64, wn = (warp & 3) * 32;
    const int r = lane >> 2, c = lane & 3;
    const int lrow = t >> 3, lc4 = (t & 7) * 4;

    #pragma unroll
    for (int i = 0; i < 16; i++){ acc[i][0]=acc[i][1]=acc[i][2]=acc[i][3]=0.f; }

    // prefetch chunk 0
    #pragma unroll
    for (int i = 0; i < 4; i++){
        cpa16(sAb[0] + (lrow + 32*i)*36 + lc4, A + (size_t)(m0 + lrow + 32*i)*DD + lc4);
        cpa16(sBb[0] + (lrow + 32*i)*36 + lc4, W + (size_t)(n0 + lrow + 32*i)*DD + lc4);
    }
    CPA_COMMIT();

    for (int ch = 0; ch < 32; ch++){
        CPA_WAIT0();
        __syncthreads();
        if (ch < 31){
            const int k0 = (ch + 1) * 32;
            float* dA = sAb[(ch + 1) & 1];
            float* dB = sBb[(ch + 1) & 1];
            #pragma unroll
            for (int i = 0; i < 4; i++){
                cpa16(dA + (lrow + 32*i)*36 + lc4, A + (size_t)(m0 + lrow + 32*i)*DD + k0 + lc4);
                cpa16(dB + (lrow + 32*i)*36 + lc4, W + (size_t)(n0 + lrow + 32*i)*DD + k0 + lc4);
            }
            CPA_COMMIT();
        }
        const float* sA = sAb[ch & 1];
        const float* sB = sBb[ch & 1];
        #pragma unroll
        for (int ks = 0; ks < 4; ks++){
            uint32_t af[4][4], bf[4][2];
            #pragma unroll
            for (int mt = 0; mt < 4; mt++){
                const float* p = sA + (wm + mt*16 + r)*36 + ks*8 + c*2;
                const float2 a02 = *(const float2*)(p);
                const float2 a13 = *(const float2*)(p + 8*36);
                af[mt][0] = __float_as_uint(a02.x);
                af[mt][1] = __float_as_uint(a13.x);
                af[mt][2] = __float_as_uint(a02.y);
                af[mt][3] = __float_as_uint(a13.y);
            }
            #pragma unroll
            for (int nt = 0; nt < 4; nt++){
                const float2 bb = *(const float2*)(sB + (wn + nt*8 + r)*36 + ks*8 + c*2);
                bf[nt][0] = __float_as_uint(bb.x);
                bf[nt][1] = __float_as_uint(bb.y);
            }
            #pragma unroll
            for (int mt = 0; mt < 4; mt++)
                #pragma unroll
                for (int nt = 0; nt < 4; nt++)
                    mma8(acc[mt*4 + nt], af[mt], bf[nt]);
        }
    }
}

// ---------------------------------------------------------------------------
// K1: QKV projection.  grid (32, 8, 3), 256 thr, 2 CTAs/SM.
// Epilogue writes q/k/v with hs-dim pair-permutation (scalar scatter within
// each 8-float window; same 32B sector, so still sector-coalesced).
// ---------------------------------------------------------------------------
extern "C" __global__ void __launch_bounds__(256, 2)
qkv_kernel(const float* __restrict__ dummy)
{
    extern __shared__ float smg[];
    const int sel = blockIdx.z;
    const float* W = g_wc + (size_t)sel * DD * DD;
    float* dst     = (sel == 0) ? g_q : ((sel == 1) ? g_k : g_v);
    const int m0 = blockIdx.x * 128, n0 = blockIdx.y * 128;
    (void)dummy;

    float acc[16][4];
    gemm_128_128(g_xc, W, m0, n0, acc, smg);

    const int lane = threadIdx.x & 31, warp = threadIdx.x >> 5;
    const int wm = (warp >> 2) * 64, wn = (warp & 3) * 32;
    const int r = lane >> 2, c = lane & 3;
    #pragma unroll
    for (int mt = 0; mt < 4; mt++){
        #pragma unroll
        for (int nt = 0; nt < 4; nt++){
            const float* f = acc[mt*4 + nt];
            const int m_ = m0 + wm + mt*16 + r;
            const int n_ = n0 + wn + nt*8 + c*2;
            const int b  = m_ >> 11, h = n_ >> 6;
            const int hs0 = p8(n_ & 63), hs1 = p8((n_ + 1) & 63);
            const int t0 = m_ & 2047, t1 = (m_ + 8) & 2047;
            float* base0 = dst + ((size_t)((b<<4) + h)*TT + t0)*HS;
            float* base1 = dst + ((size_t)((b<<4) + h)*TT + t1)*HS;
            base0[hs0] = f2tff(f[0]);
            base0[hs1] = f2tff(f[1]);
            base1[hs0] = f2tff(f[2]);
            base1[hs1] = f2tff(f[3]);
        }
    }
}

// ---------------------------------------------------------------------------
// K2: fused attention.  grid (16, 16, 2), 256 thr, 174592 B smem.
// q/k hs-permuted (transparent to QK dot).  v hs-permuted -> y lands D-permuted
// exactly as oproj's A operand needs.  Fragment feeds use LDS.64.
// Pass 1: l[q] = sum_k exp(q.k/8) (no max: |s| <= ~3.3).
// Pass 2: att = exp(s)/l -> smem P tile -> coalesced gmem store + P*V MMAs.
// ---------------------------------------------------------------------------
extern "C" __global__ void __launch_bounds__(256, 1)
attn_kernel(float* __restrict__ att)
{
    extern __shared__ float sm[];
    float* sQ = sm;                    // 128 x (64 + 4 pad)
    float* sK = sQ + 128*68;           // 128 x (64 + 4 pad)
    float* sV = sK + 128*68;           // 128 x (64 + 8 pad)
    float* sP = sV + 128*72;           // 128 x (128 + 4 pad)
    float* sL = sP + 128*132;          // 128 row sums

    const int t = threadIdx.x, lane = t & 31, warp = t >> 5;
    const int r = lane >> 2, c = lane & 3;
    const int qb = blockIdx.x, h = blockIdx.y, b = blockIdx.z;

    const size_t headoff = (size_t)(b*HH + h) * TT * HS;
    const float* Qg = g_q + headoff + (size_t)qb * 128 * HS;
    const float* Kg = g_k + headoff;
    const float* Vg = g_v + headoff;
    float* attg = att + ((size_t)(b*HH + h)*TT + (size_t)qb*128) * TT;

    // load Q tile
    #pragma unroll
    for (int i = 0; i < 8; i++){
        const int idx = t + 256*i, row = idx >> 4, col = (idx & 15) * 4;
        *(float4*)(sQ + row*68 + col) = *(const float4*)(Qg + row*64 + col);
    }
    __syncthreads();

    // preload Q A-fragments (LDS.64 pairs thanks to hs permutation)
    uint32_t aq[8][4];
    #pragma unroll
    for (int ks = 0; ks < 8; ks++){
        const float* p = sQ + (warp*16 + r)*68 + ks*8 + c*2;
        const float2 a02 = *(const float2*)(p);
        const float2 a13 = *(const float2*)(p + 8*68);
        aq[ks][0] = __float_as_uint(a02.x);
        aq[ks][1] = __float_as_uint(a13.x);
        aq[ks][2] = __float_as_uint(a02.y);
        aq[ks][3] = __float_as_uint(a13.y);
    }

    const float CF = 0.18033688011112042f;   // log2(e) / sqrt(64)

    // ---- PASS 1: row sums of exp(s) ----
    float l0 = 0.f, l1 = 0.f;
    for (int kb = 0; kb < 16; kb++){
        __syncthreads();
        #pragma unroll
        for (int i = 0; i < 8; i++){
            const int idx = t + 256*i, row = idx >> 4, col = (idx & 15) * 4;
            *(float4*)(sK + row*68 + col) = *(const float4*)(Kg + (size_t)(kb*128 + row)*64 + col);
        }
        __syncthreads();

        float s[16][4];
        #pragma unroll
        for (int i = 0; i < 16; i++){ s[i][0]=s[i][1]=s[i][2]=s[i][3]=0.f; }
        #pragma unroll
        for (int ks = 0; ks < 8; ks++){
            #pragma unroll
            for (int nt = 0; nt < 16; nt++){
                uint32_t bf[2];
                const float2 bb = *(const float2*)(sK + (nt*8 + r)*68 + ks*8 + c*2);
                bf[0] = __float_as_uint(bb.x);
                bf[1] = __float_as_uint(bb.y);
                mma8(s[nt], aq[ks], bf);
            }
        }
        #pragma unroll
        for (int nt = 0; nt < 16; nt++){
            l0 += exp2f(s[nt][0]*CF) + exp2f(s[nt][1]*CF);
            l1 += exp2f(s[nt][2]*CF) + exp2f(s[nt][3]*CF);
        }
    }
    l0 += __shfl_xor_sync(0xffffffffu, l0, 1);
    l0 += __shfl_xor_sync(0xffffffffu, l0, 2);
    l1 += __shfl_xor_sync(0xffffffffu, l1, 1);
    l1 += __shfl_xor_sync(0xffffffffu, l1, 2);
    __syncthreads();
    if (c == 0){ sL[warp*16 + r] = l0; sL[warp*16 + r + 8] = l1; }
    __syncthreads();
    const float inv0 = 1.0f / sL[warp*16 + r];
    const float inv1 = 1.0f / sL[warp*16 + r + 8];

    // ---- PASS 2: att store + P*V ----
    float yv[8][4];
    #pragma unroll
    for (int i = 0; i < 8; i++){ yv[i][0]=yv[i][1]=yv[i][2]=yv[i][3]=0.f; }

    for (int kb = 0; kb < 16; kb++){
        __syncthreads();
        #pragma unroll
        for (int i = 0; i < 8; i++){
            const int idx = t + 256*i, row = idx >> 4, col = (idx & 15) * 4;
            *(float4*)(sK + row*68 + col) = *(const float4*)(Kg + (size_t)(kb*128 + row)*64 + col);
            *(float4*)(sV + row*72 + col) = *(const float4*)(Vg + (size_t)(kb*128 + row)*64 + col);
        }
        __syncthreads();

        float s[16][4];
        #pragma unroll
        for (int i = 0; i < 16; i++){ s[i][0]=s[i][1]=s[i][2]=s[i][3]=0.f; }
        #pragma unroll
        for (int ks = 0; ks < 8; ks++){
            #pragma unroll
            for (int nt = 0; nt < 16; nt++){
                uint32_t bf[2];
                const float2 bb = *(const float2*)(sK + (nt*8 + r)*68 + ks*8 + c*2);
                bf[0] = __float_as_uint(bb.x);
                bf[1] = __float_as_uint(bb.y);
                mma8(s[nt], aq[ks], bf);
            }
        }
        // normalized probabilities -> smem P tile (natural key order: C-frag
        // cols are 2c,2c+1 which are contiguous already)
        #pragma unroll
        for (int nt = 0; nt < 16; nt++){
            float p0 = exp2f(s[nt][0]*CF) * inv0;
            float p1 = exp2f(s[nt][1]*CF) * inv0;
            float p2 = exp2f(s[nt][2]*CF) * inv1;
            float p3 = exp2f(s[nt][3]*CF) * inv1;
            float* pp = sP + (warp*16 + r)*132 + nt*8 + 2*c;
            *(float2*)(pp)         = make_float2(p0, p1);
            *(float2*)(pp + 8*132) = make_float2(p2, p3);
        }
        __syncthreads();

        // coalesced att store (one warp per row, float4)
        #pragma unroll
        for (int i = 0; i < 16; i++){
            const int idx = t + 256*i, row = idx >> 5, c4 = (idx & 31) * 4;
            *(float4*)(attg + (size_t)row*TT + kb*128 + c4) = *(const float4*)(sP + row*132 + c4);
        }
        // Y += P * V   (keys natural on both operands -> consistent)
        #pragma unroll
        for (int ks = 0; ks < 16; ks++){
            uint32_t ap[4];
            const float* p = sP + (warp*16 + r)*132 + ks*8 + c;
            ap[0] = __float_as_uint(p[0]);
            ap[1] = __float_as_uint(p[8*132]);
            ap[2] = __float_as_uint(p[4]);
            ap[3] = __float_as_uint(p[8*132 + 4]);
            #pragma unroll
            for (int nt = 0; nt < 8; nt++){
                uint32_t bv[2];
                const float* q2 = sV + (ks*8 + c)*72 + nt*8 + r;
                bv[0] = __float_as_uint(q2[0]);
                bv[1] = __float_as_uint(q2[4*72]);
                mma8(yv[nt], ap, bv);
            }
        }
    }

    // write Y (tf32-rounded).  n-index already refers to permuted hs (v was
    // permuted), so linear store yields D-pair-permuted y = oproj's A layout.
    #pragma unroll
    for (int nt = 0; nt < 8; nt++){
        const int row = qb*128 + warp*16 + r;
        const int col = h*64 + nt*8 + 2*c;
        *(float2*)(g_y + ((size_t)b*TT + row)*DD + col)     = make_float2(f2tff(yv[nt][0]), f2tff(yv[nt][1]));
        *(float2*)(g_y + ((size_t)b*TT + row + 8)*DD + col) = make_float2(f2tff(yv[nt][2]), f2tff(yv[nt][3]));
    }
}

// ---------------------------------------------------------------------------
// K3: output projection + bias.  grid (32, 8), 256 thr, 2 CTAs/SM.
// A = g_y (D-permuted), B = Wo (D-permuted) -> transparent.  Output natural.
// ---------------------------------------------------------------------------
extern "C" __global__ void __launch_bounds__(256, 2)
oproj_kernel(const float* __restrict__ bo, float* __restrict__ out)
{
    extern __shared__ float smg[];
    const int m0 = blockIdx.x * 128, n0 = blockIdx.y * 128;

    float acc[16][4];
    gemm_128_128(g_y, g_wc + (size_t)3*DD*DD, m0, n0, acc, smg);

    const int lane = threadIdx.x & 31, warp = threadIdx.x >> 5;
    const int wm = (warp >> 2) * 64, wn = (warp & 3) * 32;
    const int r = lane >> 2, c = lane & 3;
    #pragma unroll
    for (int mt = 0; mt < 4; mt++){
        #pragma unroll
        for (int nt = 0; nt < 4; nt++){
            const float* f = acc[mt*4 + nt];
            const int m_ = m0 + wm + mt*16 + r;
            const int n_ = n0 + wn + nt*8 + c*2;
            const float2 bias = *(const float2*)(bo + n_);
            float2 v0 = make_float2(f[0] + bias.x, f[1] + bias.y);
            float2 v1 = make_float2(f[2] + bias.x, f[3] + bias.y);
            *(float2*)(out + (size_t)m_*DD + n_)       = v0;
            *(float2*)(out + (size_t)(m_ + 8)*DD + n_) = v1;
        }
    }
}

// ---------------------------------------------------------------------------
extern "C" void kernel_launch(void* const* d_in, const int* in_sizes, int n_in,
                              void* d_out, int out_size)
{
    (void)in_sizes; (void)n_in; (void)out_size;
    const float* x  = (const float*)d_in[0];
    const float* Wq = (const float*)d_in[1];
    const float* Wk = (const float*)d_in[2];
    const float* Wv = (const float*)d_in[3];
    const float* Wo = (const float*)d_in[4];
    const float* bo = (const float*)d_in[5];

    float* y_out = (float*)d_out;                       // [B,T,D]
    float* att   = y_out + (size_t)BT * DD;             // [B,H,T,T]

    const int gemm_smem = 18432 * 4;    // 73728 B (double-buffered A+B)
    const int attn_smem = (128*68 + 128*68 + 128*72 + 128*132 + 128) * 4;   // 174592 B
    cudaFuncSetAttribute(qkv_kernel,   cudaFuncAttributeMaxDynamicSharedMemorySize, gemm_smem);
    cudaFuncSetAttribute(oproj_kernel, cudaFuncAttributeMaxDynamicSharedMemorySize, gemm_smem);
    cudaFuncSetAttribute(attn_kernel,  cudaFuncAttributeMaxDynamicSharedMemorySize, attn_smem);

    conv_kernel<<<dim3(1024, 5), 256>>>(x, Wq, Wk, Wv, Wo);
    qkv_kernel<<<dim3(32, 8, 3), 256, gemm_smem>>>(x);
    attn_kernel<<<dim3(16, 16, 2), 256, attn_smem>>>(att);
    oproj_kernel<<<dim3(32, 8), 256, gemm_smem>>>(bo, y_out);
}

// round 11
// speedup vs baseline: 1.2993x; 1.2993x over previous
#include <cuda_runtime.h>
#include <cstdint>
#include <cstddef>

#define BB 2
#define TT 2048
#define DD 1024
#define HH 16
#define HS 64
#define BT (BB*TT)

// Scratch (allocation-free rule: __device__ globals)
__device__ float g_q[BB*HH*TT*HS];
__device__ float g_k[BB*HH*TT*HS];
__device__ float g_v[BB*HH*TT*HS];
__device__ float g_y[BT*DD];

__device__ __forceinline__ uint32_t f2tf(float x){
    uint32_t r; asm("cvt.rna.tf32.f32 %0, %1;" : "=r"(r) : "f"(x)); return r;
}
__device__ __forceinline__ float f2tff(float x){ return __uint_as_float(f2tf(x)); }

__device__ __forceinline__ void mma8(float* c, const uint32_t* a, const uint32_t* b){
    asm volatile(
        "mma.sync.aligned.m16n8k8.row.col.f32.tf32.tf32.f32 "
        "{%0,%1,%2,%3}, {%4,%5,%6,%7}, {%8,%9}, {%0,%1,%2,%3};\n"
        : "+f"(c[0]), "+f"(c[1]), "+f"(c[2]), "+f"(c[3])
        : "r"(a[0]), "r"(a[1]), "r"(a[2]), "r"(a[3]), "r"(b[0]), "r"(b[1]));
}

// ---------------------------------------------------------------------------
// 128x128 tile of A(MxK row-major) * W^T (W is NxK row-major), K = DD = 1024.
// (Exact R3 structure: best-measured GEMM variant.)
// 256 threads, 8 warps; warp tile 64x32 (4 m-frags x 4 n-frags of m16n8).
// ---------------------------------------------------------------------------
__device__ __forceinline__ void gemm_128_128(
    const float* __restrict__ A, const float* __restrict__ W,
    int m0, int n0, float acc[16][4], float* sA, float* sB)
{
    const int t = threadIdx.x, lane = t & 31, warp = t >> 5;
    const int wm = (warp >> 2) * 64, wn = (warp & 3) * 32;
    const int r = lane >> 2, c = lane & 3;
    const int lrow = t >> 3, lc4 = (t & 7) * 4;

    float4 ra[4], rb[4];
    #pragma unroll
    for (int i = 0; i < 4; i++){
        ra[i] = *(const float4*)(A + (size_t)(m0 + lrow + 32*i)*DD + lc4);
        rb[i] = *(const float4*)(W + (size_t)(n0 + lrow + 32*i)*DD + lc4);
    }
    #pragma unroll
    for (int i = 0; i < 16; i++){ acc[i][0]=acc[i][1]=acc[i][2]=acc[i][3]=0.f; }

    for (int k0 = 0; k0 < DD; k0 += 32){
        #pragma unroll
        for (int i = 0; i < 4; i++){
            float4 ca, cb;
            ca.x=f2tff(ra[i].x); ca.y=f2tff(ra[i].y); ca.z=f2tff(ra[i].z); ca.w=f2tff(ra[i].w);
            cb.x=f2tff(rb[i].x); cb.y=f2tff(rb[i].y); cb.z=f2tff(rb[i].z); cb.w=f2tff(rb[i].w);
            *(float4*)(sA + (lrow + 32*i)*36 + lc4) = ca;
            *(float4*)(sB + (lrow + 32*i)*36 + lc4) = cb;
        }
        __syncthreads();
        const bool nxt = (k0 + 32) < DD;
        if (nxt){
            #pragma unroll
            for (int i = 0; i < 4; i++){
                ra[i] = *(const float4*)(A + (size_t)(m0 + lrow + 32*i)*DD + k0 + 32 + lc4);
                rb[i] = *(const float4*)(W + (size_t)(n0 + lrow + 32*i)*DD + k0 + 32 + lc4);
            }
        }
        #pragma unroll
        for (int ks = 0; ks < 4; ks++){
            uint32_t af[4][4], bf[4][2];
            #pragma unroll
            for (int mt = 0; mt < 4; mt++){
                const float* p = sA + (wm + mt*16 + r)*36 + ks*8 + c;
                af[mt][0] = __float_as_uint(p[0]);
                af[mt][1] = __float_as_uint(p[8*36]);
                af[mt][2] = __float_as_uint(p[4]);
                af[mt][3] = __float_as_uint(p[8*36 + 4]);
            }
            #pragma unroll
            for (int nt = 0; nt < 4; nt++){
                const float* p = sB + (wn + nt*8 + r)*36 + ks*8 + c;
                bf[nt][0] = __float_as_uint(p[0]);
                bf[nt][1] = __float_as_uint(p[4]);
            }
            #pragma unroll
            for (int mt = 0; mt < 4; mt++)
                #pragma unroll
                for (int nt = 0; nt < 4; nt++)
                    mma8(acc[mt*4 + nt], af[mt], bf[nt]);
        }
        __syncthreads();
    }
}

// ---------------------------------------------------------------------------
// K1: QKV projection (exact R3).  grid (32, 8, 3), 256 thr.
// ---------------------------------------------------------------------------
extern "C" __global__ void __launch_bounds__(256, 1)
qkv_kernel(const float* __restrict__ x, const float* __restrict__ Wq,
           const float* __restrict__ Wk, const float* __restrict__ Wv)
{
    __shared__ float sA[128*36];
    __shared__ float sB[128*36];
    const float* W = (blockIdx.z == 0) ? Wq : ((blockIdx.z == 1) ? Wk : Wv);
    float* dst     = (blockIdx.z == 0) ? g_q : ((blockIdx.z == 1) ? g_k : g_v);
    const int m0 = blockIdx.x * 128, n0 = blockIdx.y * 128;

    float acc[16][4];
    gemm_128_128(x, W, m0, n0, acc, sA, sB);

    const int lane = threadIdx.x & 31, warp = threadIdx.x >> 5;
    const int wm = (warp >> 2) * 64, wn = (warp & 3) * 32;
    const int r = lane >> 2, c = lane & 3;
    #pragma unroll
    for (int mt = 0; mt < 4; mt++){
        #pragma unroll
        for (int nt = 0; nt < 4; nt++){
            const float* f = acc[mt*4 + nt];
            const int m_ = m0 + wm + mt*16 + r;
            const int n_ = n0 + wn + nt*8 + c*2;
            const int b  = m_ >> 11, h = n_ >> 6, hs = n_ & 63;
            const int t0 = m_ & 2047, t1 = (m_ + 8) & 2047;
            float2 v0 = make_float2(f2tff(f[0]), f2tff(f[1]));
            float2 v1 = make_float2(f2tff(f[2]), f2tff(f[3]));
            *(float2*)(dst + ((size_t)((b<<4) + h)*TT + t0)*HS + hs) = v0;
            *(float2*)(dst + ((size_t)((b<<4) + h)*TT + t1)*HS + hs) = v1;
        }
    }
}

// ---------------------------------------------------------------------------
// K2: fused attention v2.  grid (16, 16, 2), 256 thr, 2 CTAs/SM.
//  - no sP tile: att stored directly from C-fragments (sector-perfect STG.64)
//  - P*V A-fragments come straight from registers: V smem tile is stored with
//    k-rows permuted by sigma (even u -> u/2, odd u -> 4 + u/2), which makes
//    the C-frag->A-frag identity mapping {p0,p2,p1,p3} exact.
//  - nt processed in 2 chunks of 8 to keep S fragments at 32 regs.
//  - smem 104.5 KB -> 2 CTAs/SM.
// Pass 1: l[q] = sum_k exp(q.k/8) (no max: |s| <= ~3.3).
// ---------------------------------------------------------------------------
extern "C" __global__ void __launch_bounds__(256, 2)
attn_kernel(float* __restrict__ att)
{
    extern __shared__ float sm[];
    float* sQ = sm;                    // 128 x 68
    float* sK = sQ + 128*68;           // 128 x 68
    float* sV = sK + 128*68;           // 128 x 72 (k-rows sigma-permuted)
    float* sL = sV + 128*72;           // 128 row sums

    const int t = threadIdx.x, lane = t & 31, warp = t >> 5;
    const int r = lane >> 2, c = lane & 3;
    const int qb = blockIdx.x, h = blockIdx.y, b = blockIdx.z;

    const size_t headoff = (size_t)(b*HH + h) * TT * HS;
    const float* Qg = g_q + headoff + (size_t)qb * 128 * HS;
    const float* Kg = g_k + headoff;
    const float* Vg = g_v + headoff;
    float* attg = att + ((size_t)(b*HH + h)*TT + (size_t)qb*128) * TT;

    // load Q tile
    #pragma unroll
    for (int i = 0; i < 8; i++){
        const int idx = t + 256*i, row = idx >> 4, col = (idx & 15) * 4;
        *(float4*)(sQ + row*68 + col) = *(const float4*)(Qg + row*64 + col);
    }
    __syncthreads();

    // preload Q A-fragments (fixed for whole CTA lifetime)
    uint32_t aq[8][4];
    #pragma unroll
    for (int ks = 0; ks < 8; ks++){
        const float* p = sQ + (warp*16 + r)*68 + ks*8 + c;
        aq[ks][0] = __float_as_uint(p[0]);
        aq[ks][1] = __float_as_uint(p[8*68]);
        aq[ks][2] = __float_as_uint(p[4]);
        aq[ks][3] = __float_as_uint(p[8*68 + 4]);
    }

    const float CF = 0.18033688011112042f;   // log2(e) / sqrt(64)

    // ---- PASS 1: row sums of exp(s) ----
    float l0 = 0.f, l1 = 0.f;
    for (int kb = 0; kb < 16; kb++){
        __syncthreads();
        #pragma unroll
        for (int i = 0; i < 8; i++){
            const int idx = t + 256*i, row = idx >> 4, col = (idx & 15) * 4;
            *(float4*)(sK + row*68 + col) = *(const float4*)(Kg + (size_t)(kb*128 + row)*64 + col);
        }
        __syncthreads();

        #pragma unroll
        for (int ntc = 0; ntc < 2; ntc++){
            float s[8][4];
            #pragma unroll
            for (int i = 0; i < 8; i++){ s[i][0]=s[i][1]=s[i][2]=s[i][3]=0.f; }
            #pragma unroll
            for (int ks = 0; ks < 8; ks++){
                #pragma unroll
                for (int nt = 0; nt < 8; nt++){
                    uint32_t bf[2];
                    const float* p = sK + ((ntc*8 + nt)*8 + r)*68 + ks*8 + c;
                    bf[0] = __float_as_uint(p[0]);
                    bf[1] = __float_as_uint(p[4]);
                    mma8(s[nt], aq[ks], bf);
                }
            }
            #pragma unroll
            for (int nt = 0; nt < 8; nt++){
                l0 += exp2f(s[nt][0]*CF) + exp2f(s[nt][1]*CF);
                l1 += exp2f(s[nt][2]*CF) + exp2f(s[nt][3]*CF);
            }
        }
    }
    l0 += __shfl_xor_sync(0xffffffffu, l0, 1);
    l0 += __shfl_xor_sync(0xffffffffu, l0, 2);
    l1 += __shfl_xor_sync(0xffffffffu, l1, 1);
    l1 += __shfl_xor_sync(0xffffffffu, l1, 2);
    __syncthreads();
    if (c == 0){ sL[warp*16 + r] = l0; sL[warp*16 + r + 8] = l1; }
    __syncthreads();
    const float inv0 = 1.0f / sL[warp*16 + r];
    const float inv1 = 1.0f / sL[warp*16 + r + 8];

    // ---- PASS 2: direct att store + register-P P*V ----
    float yv[8][4];
    #pragma unroll
    for (int i = 0; i < 8; i++){ yv[i][0]=yv[i][1]=yv[i][2]=yv[i][3]=0.f; }

    const int qrow = warp*16 + r;
    float* att0 = attg + (size_t)qrow * TT;
    float* att1 = attg + (size_t)(qrow + 8) * TT;

    for (int kb = 0; kb < 16; kb++){
        __syncthreads();
        #pragma unroll
        for (int i = 0; i < 8; i++){
            const int idx = t + 256*i, row = idx >> 4, col = (idx & 15) * 4;
            *(float4*)(sK + row*68 + col) = *(const float4*)(Kg + (size_t)(kb*128 + row)*64 + col);
            // V: sigma-permute k-row within its 8-group
            const int u = row & 7;
            const int rowp = (row & ~7) | ((u & 1) ? (4 + (u >> 1)) : (u >> 1));
            *(float4*)(sV + rowp*72 + col) = *(const float4*)(Vg + (size_t)(kb*128 + row)*64 + col);
        }
        __syncthreads();

        #pragma unroll
        for (int ntc = 0; ntc < 2; ntc++){
            float s[8][4];
            #pragma unroll
            for (int i = 0; i < 8; i++){ s[i][0]=s[i][1]=s[i][2]=s[i][3]=0.f; }
            #pragma unroll
            for (int ks = 0; ks < 8; ks++){
                #pragma unroll
                for (int nt = 0; nt < 8; nt++){
                    uint32_t bf[2];
                    const float* p = sK + ((ntc*8 + nt)*8 + r)*68 + ks*8 + c;
                    bf[0] = __float_as_uint(p[0]);
                    bf[1] = __float_as_uint(p[4]);
                    mma8(s[nt], aq[ks], bf);
                }
            }
            #pragma unroll
            for (int nt = 0; nt < 8; nt++){
                const int g = ntc*8 + nt;               // S col-group == PV k-group
                const float p0 = exp2f(s[nt][0]*CF) * inv0;
                const float p1 = exp2f(s[nt][1]*CF) * inv0;
                const float p2 = exp2f(s[nt][2]*CF) * inv1;
                const float p3 = exp2f(s[nt][3]*CF) * inv1;
                // direct att store (one 32B sector per row per group)
                const int colb = kb*128 + g*8 + 2*c;
                *(float2*)(att0 + colb) = make_float2(p0, p1);
                *(float2*)(att1 + colb) = make_float2(p2, p3);
                // P as A-fragment (C->A identity under sigma-permuted V)
                uint32_t ap[4];
                ap[0] = __float_as_uint(p0);
                ap[1] = __float_as_uint(p2);
                ap[2] = __float_as_uint(p1);
                ap[3] = __float_as_uint(p3);
                #pragma unroll
                for (int ntv = 0; ntv < 8; ntv++){
                    uint32_t bv[2];
                    const float* q2 = sV + (g*8 + c)*72 + ntv*8 + r;
                    bv[0] = __float_as_uint(q2[0]);
                    bv[1] = __float_as_uint(q2[4*72]);
                    mma8(yv[ntv], ap, bv);
                }
            }
        }
    }

    // write Y to g_y in [B,T,D] layout
    #pragma unroll
    for (int nt = 0; nt < 8; nt++){
        const int row = qb*128 + warp*16 + r;
        const int col = h*64 + nt*8 + 2*c;
        *(float2*)(g_y + ((size_t)b*TT + row)*DD + col)     = make_float2(yv[nt][0], yv[nt][1]);
        *(float2*)(g_y + ((size_t)b*TT + row + 8)*DD + col) = make_float2(yv[nt][2], yv[nt][3]);
    }
}

// ---------------------------------------------------------------------------
// K3: output projection + bias (exact R3).  grid (32, 8), 256 thr.
// ---------------------------------------------------------------------------
extern "C" __global__ void __launch_bounds__(256, 1)
oproj_kernel(const float* __restrict__ Wo, const float* __restrict__ bo,
             float* __restrict__ out)
{
    __shared__ float sA[128*36];
    __shared__ float sB[128*36];
    const int m0 = blockIdx.x * 128, n0 = blockIdx.y * 128;

    float acc[16][4];
    gemm_128_128(g_y, Wo, m0, n0, acc, sA, sB);

    const int lane = threadIdx.x & 31, warp = threadIdx.x >> 5;
    const int wm = (warp >> 2) * 64, wn = (warp & 3) * 32;
    const int r = lane >> 2, c = lane & 3;
    #pragma unroll
    for (int mt = 0; mt < 4; mt++){
        #pragma unroll
        for (int nt = 0; nt < 4; nt++){
            const float* f = acc[mt*4 + nt];
            const int m_ = m0 + wm + mt*16 + r;
            const int n_ = n0 + wn + nt*8 + c*2;
            const float2 bias = *(const float2*)(bo + n_);
            float2 v0 = make_float2(f[0] + bias.x, f[1] + bias.y);
            float2 v1 = make_float2(f[2] + bias.x, f[3] + bias.y);
            *(float2*)(out + (size_t)m_*DD + n_)       = v0;
            *(float2*)(out + (size_t)(m_ + 8)*DD + n_) = v1;
        }
    }
}

// ---------------------------------------------------------------------------
extern "C" void kernel_launch(void* const* d_in, const int* in_sizes, int n_in,
                              void* d_out, int out_size)
{
    (void)in_sizes; (void)n_in; (void)out_size;
    const float* x  = (const float*)d_in[0];
    const float* Wq = (const float*)d_in[1];
    const float* Wk = (const float*)d_in[2];
    const float* Wv = (const float*)d_in[3];
    const float* Wo = (const float*)d_in[4];
    const float* bo = (const float*)d_in[5];

    float* y_out = (float*)d_out;                       // [B,T,D]
    float* att   = y_out + (size_t)BT * DD;             // [B,H,T,T]

    const int attn_smem = (128*68 + 128*68 + 128*72 + 128) * 4;   // 107008 B
    cudaFuncSetAttribute(attn_kernel, cudaFuncAttributeMaxDynamicSharedMemorySize, attn_smem);

    qkv_kernel<<<dim3(32, 8, 3), 256>>>(x, Wq, Wk, Wv);
    attn_kernel<<<dim3(16, 16, 2), 256, attn_smem>>>(att);
    oproj_kernel<<<dim3(32, 8), 256>>>(Wo, bo, y_out);
}

// round 12
// speedup vs baseline: 1.3182x; 1.0146x over previous
#include <cuda_runtime.h>
#include <cstdint>
#include <cstddef>

#define BB 2
#define TT 2048
#define DD 1024
#define HH 16
#define HS 64
#define BT (BB*TT)

// Scratch (allocation-free rule: __device__ globals)
__device__ float g_q[BB*HH*TT*HS];
__device__ float g_k[BB*HH*TT*HS];
__device__ float g_v[BB*HH*TT*HS];
__device__ float g_y[BT*DD];         // tf32-rounded by attn epilogue
__device__ float g_xc[BT*DD];        // tf32-rounded x
__device__ float g_wc[4*DD*DD];      // tf32-rounded Wq,Wk,Wv,Wo

__device__ __forceinline__ uint32_t f2tf(float x){
    uint32_t r; asm("cvt.rna.tf32.f32 %0, %1;" : "=r"(r) : "f"(x)); return r;
}
__device__ __forceinline__ float f2tff(float x){ return __uint_as_float(f2tf(x)); }

__device__ __forceinline__ void mma8(float* c, const uint32_t* a, const uint32_t* b){
    asm volatile(
        "mma.sync.aligned.m16n8k8.row.col.f32.tf32.tf32.f32 "
        "{%0,%1,%2,%3}, {%4,%5,%6,%7}, {%8,%9}, {%0,%1,%2,%3};\n"
        : "+f"(c[0]), "+f"(c[1]), "+f"(c[2]), "+f"(c[3])
        : "r"(a[0]), "r"(a[1]), "r"(a[2]), "r"(a[3]), "r"(b[0]), "r"(b[1]));
}

__device__ __forceinline__ void cpa16(float* dst_smem, const float* src){
    uint32_t d = (uint32_t)__cvta_generic_to_shared(dst_smem);
    asm volatile("cp.async.cg.shared.global [%0], [%1], 16;\n" :: "r"(d), "l"(src));
}
#define CPA_COMMIT() asm volatile("cp.async.commit_group;\n" ::: "memory")
#define CPA_WAIT0()  asm volatile("cp.async.wait_group 0;\n" ::: "memory")

// ---------------------------------------------------------------------------
// conv: tf32-round x and the 4 weights once (cvt.rna -> same values the old
// staging-time cvt produced; GEMM mainloops then carry ZERO cvt).
// grid (256, 5), 256 thr.
// ---------------------------------------------------------------------------
extern "C" __global__ void __launch_bounds__(256)
conv_kernel(const float* __restrict__ x,  const float* __restrict__ Wq,
            const float* __restrict__ Wk, const float* __restrict__ Wv,
            const float* __restrict__ Wo)
{
    const float4* src; float4* dst; int n4;
    switch (blockIdx.y){
        case 0:  src = (const float4*)x;  dst = (float4*)g_xc;             n4 = BT*DD/4; break;
        case 1:  src = (const float4*)Wq; dst = (float4*)(g_wc);           n4 = DD*DD/4; break;
        case 2:  src = (const float4*)Wk; dst = (float4*)(g_wc + DD*DD);   n4 = DD*DD/4; break;
        case 3:  src = (const float4*)Wv; dst = (float4*)(g_wc + 2*DD*DD); n4 = DD*DD/4; break;
        default: src = (const float4*)Wo; dst = (float4*)(g_wc + 3*DD*DD); n4 = DD*DD/4; break;
    }
    for (int i = blockIdx.x*blockDim.x + threadIdx.x; i < n4; i += gridDim.x*blockDim.x){
        float4 v = src[i];
        v.x = f2tff(v.x); v.y = f2tff(v.y); v.z = f2tff(v.z); v.w = f2tff(v.w);
        dst[i] = v;
    }
}

// ---------------------------------------------------------------------------
// 128x128 tile of A(MxK row-major) * W^T (W is NxK row-major), K = DD = 1024.
// Inputs pre-rounded to tf32 in gmem: mainloop = cp.async + LDS + MMA only.
// Double-buffered, k-chunk 32, ONE barrier per chunk. 256 thr, 8 warps,
// warp tile 64x32.  No staging registers, no cvt -> fits 2 CTAs/SM.
// ---------------------------------------------------------------------------
__device__ __forceinline__ void gemm_128_128_async(
    const float* __restrict__ A, const float* __restrict__ W,
    int m0, int n0, float acc[16][4], float* sm)
{
    float* sAb[2] = { sm,          sm + 4608 };
    float* sBb[2] = { sm + 9216,   sm + 13824 };

    const int t = threadIdx.x, lane = t & 31, warp = t >> 5;
    const int wm = (warp >> 2) * 64, wn = (warp & 3) * 32;
    const int r = lane >> 2, c = lane & 3;
    const int lrow = t >> 3, lc4 = (t & 7) * 4;

    #pragma unroll
    for (int i = 0; i < 16; i++){ acc[i][0]=acc[i][1]=acc[i][2]=acc[i][3]=0.f; }

    // prefetch chunk 0
    #pragma unroll
    for (int i = 0; i < 4; i++){
        cpa16(sAb[0] + (lrow + 32*i)*36 + lc4, A + (size_t)(m0 + lrow + 32*i)*DD + lc4);
        cpa16(sBb[0] + (lrow + 32*i)*36 + lc4, W + (size_t)(n0 + lrow + 32*i)*DD + lc4);
    }
    CPA_COMMIT();

    for (int ch = 0; ch < 32; ch++){
        CPA_WAIT0();
        __syncthreads();
        if (ch < 31){
            const int k0 = (ch + 1) * 32;
            float* dA = sAb[(ch + 1) & 1];
            float* dB = sBb[(ch + 1) & 1];
            #pragma unroll
            for (int i = 0; i < 4; i++){
                cpa16(dA + (lrow + 32*i)*36 + lc4, A + (size_t)(m0 + lrow + 32*i)*DD + k0 + lc4);
                cpa16(dB + (lrow + 32*i)*36 + lc4, W + (size_t)(n0 + lrow + 32*i)*DD + k0 + lc4);
            }
            CPA_COMMIT();
        }
        const float* sA = sAb[ch & 1];
        const float* sB = sBb[ch & 1];
        #pragma unroll
        for (int ks = 0; ks < 4; ks++){
            uint32_t af[4][4], bf[4][2];
            #pragma unroll
            for (int mt = 0; mt < 4; mt++){
                const float* p = sA + (wm + mt*16 + r)*36 + ks*8 + c;
                af[mt][0] = __float_as_uint(p[0]);
                af[mt][1] = __float_as_uint(p[8*36]);
                af[mt][2] = __float_as_uint(p[4]);
                af[mt][3] = __float_as_uint(p[8*36 + 4]);
            }
            #pragma unroll
            for (int nt = 0; nt < 4; nt++){
                const float* p = sB + (wn + nt*8 + r)*36 + ks*8 + c;
                bf[nt][0] = __float_as_uint(p[0]);
                bf[nt][1] = __float_as_uint(p[4]);
            }
            #pragma unroll
            for (int mt = 0; mt < 4; mt++)
                #pragma unroll
                for (int nt = 0; nt < 4; nt++)
                    mma8(acc[mt*4 + nt], af[mt], bf[nt]);
        }
    }
}

// ---------------------------------------------------------------------------
// K1: QKV projection.  grid (32, 8, 3), 256 thr, 2 CTAs/SM.
// ---------------------------------------------------------------------------
extern "C" __global__ void __launch_bounds__(256, 2)
qkv_kernel()
{
    extern __shared__ float smg[];
    const int sel = blockIdx.z;
    const float* W = g_wc + (size_t)sel * DD * DD;
    float* dst     = (sel == 0) ? g_q : ((sel == 1) ? g_k : g_v);
    const int m0 = blockIdx.x * 128, n0 = blockIdx.y * 128;

    float acc[16][4];
    gemm_128_128_async(g_xc, W, m0, n0, acc, smg);

    const int lane = threadIdx.x & 31, warp = threadIdx.x >> 5;
    const int wm = (warp >> 2) * 64, wn = (warp & 3) * 32;
    const int r = lane >> 2, c = lane & 3;
    #pragma unroll
    for (int mt = 0; mt < 4; mt++){
        #pragma unroll
        for (int nt = 0; nt < 4; nt++){
            const float* f = acc[mt*4 + nt];
            const int m_ = m0 + wm + mt*16 + r;
            const int n_ = n0 + wn + nt*8 + c*2;
            const int b  = m_ >> 11, h = n_ >> 6, hs = n_ & 63;
            const int t0 = m_ & 2047, t1 = (m_ + 8) & 2047;
            float2 v0 = make_float2(f2tff(f[0]), f2tff(f[1]));
            float2 v1 = make_float2(f2tff(f[2]), f2tff(f[3]));
            *(float2*)(dst + ((size_t)((b<<4) + h)*TT + t0)*HS + hs) = v0;
            *(float2*)(dst + ((size_t)((b<<4) + h)*TT + t1)*HS + hs) = v1;
        }
    }
}

// ---------------------------------------------------------------------------
// K2: fused attention v2 (unchanged from R11 winner; y now tf32-rounded at
// write, which matches oproj's old staging-time cvt bit-for-bit).
// grid (16, 16, 2), 256 thr, 2 CTAs/SM, smem 107008 B.
// ---------------------------------------------------------------------------
extern "C" __global__ void __launch_bounds__(256, 2)
attn_kernel(float* __restrict__ att)
{
    extern __shared__ float sm[];
    float* sQ = sm;                    // 128 x 68
    float* sK = sQ + 128*68;           // 128 x 68
    float* sV = sK + 128*68;           // 128 x 72 (k-rows sigma-permuted)
    float* sL = sV + 128*72;           // 128 row sums

    const int t = threadIdx.x, lane = t & 31, warp = t >> 5;
    const int r = lane >> 2, c = lane & 3;
    const int qb = blockIdx.x, h = blockIdx.y, b = blockIdx.z;

    const size_t headoff = (size_t)(b*HH + h) * TT * HS;
    const float* Qg = g_q + headoff + (size_t)qb * 128 * HS;
    const float* Kg = g_k + headoff;
    const float* Vg = g_v + headoff;
    float* attg = att + ((size_t)(b*HH + h)*TT + (size_t)qb*128) * TT;

    // load Q tile
    #pragma unroll
    for (int i = 0; i < 8; i++){
        const int idx = t + 256*i, row = idx >> 4, col = (idx & 15) * 4;
        *(float4*)(sQ + row*68 + col) = *(const float4*)(Qg + row*64 + col);
    }
    __syncthreads();

    // preload Q A-fragments (fixed for whole CTA lifetime)
    uint32_t aq[8][4];
    #pragma unroll
    for (int ks = 0; ks < 8; ks++){
        const float* p = sQ + (warp*16 + r)*68 + ks*8 + c;
        aq[ks][0] = __float_as_uint(p[0]);
        aq[ks][1] = __float_as_uint(p[8*68]);
        aq[ks][2] = __float_as_uint(p[4]);
        aq[ks][3] = __float_as_uint(p[8*68 + 4]);
    }

    const float CF = 0.18033688011112042f;   // log2(e) / sqrt(64)

    // ---- PASS 1: row sums of exp(s) ----
    float l0 = 0.f, l1 = 0.f;
    for (int kb = 0; kb < 16; kb++){
        __syncthreads();
        #pragma unroll
        for (int i = 0; i < 8; i++){
            const int idx = t + 256*i, row = idx >> 4, col = (idx & 15) * 4;
            *(float4*)(sK + row*68 + col) = *(const float4*)(Kg + (size_t)(kb*128 + row)*64 + col);
        }
        __syncthreads();

        #pragma unroll
        for (int ntc = 0; ntc < 2; ntc++){
            float s[8][4];
            #pragma unroll
            for (int i = 0; i < 8; i++){ s[i][0]=s[i][1]=s[i][2]=s[i][3]=0.f; }
            #pragma unroll
            for (int ks = 0; ks < 8; ks++){
                #pragma unroll
                for (int nt = 0; nt < 8; nt++){
                    uint32_t bf[2];
                    const float* p = sK + ((ntc*8 + nt)*8 + r)*68 + ks*8 + c;
                    bf[0] = __float_as_uint(p[0]);
                    bf[1] = __float_as_uint(p[4]);
                    mma8(s[nt], aq[ks], bf);
                }
            }
            #pragma unroll
            for (int nt = 0; nt < 8; nt++){
                l0 += exp2f(s[nt][0]*CF) + exp2f(s[nt][1]*CF);
                l1 += exp2f(s[nt][2]*CF) + exp2f(s[nt][3]*CF);
            }
        }
    }
    l0 += __shfl_xor_sync(0xffffffffu, l0, 1);
    l0 += __shfl_xor_sync(0xffffffffu, l0, 2);
    l1 += __shfl_xor_sync(0xffffffffu, l1, 1);
    l1 += __shfl_xor_sync(0xffffffffu, l1, 2);
    __syncthreads();
    if (c == 0){ sL[warp*16 + r] = l0; sL[warp*16 + r + 8] = l1; }
    __syncthreads();
    const float inv0 = 1.0f / sL[warp*16 + r];
    const float inv1 = 1.0f / sL[warp*16 + r + 8];

    // ---- PASS 2: direct att store + register-P P*V ----
    float yv[8][4];
    #pragma unroll
    for (int i = 0; i < 8; i++){ yv[i][0]=yv[i][1]=yv[i][2]=yv[i][3]=0.f; }

    const int qrow = warp*16 + r;
    float* att0 = attg + (size_t)qrow * TT;
    float* att1 = attg + (size_t)(qrow + 8) * TT;

    for (int kb = 0; kb < 16; kb++){
        __syncthreads();
        #pragma unroll
        for (int i = 0; i < 8; i++){
            const int idx = t + 256*i, row = idx >> 4, col = (idx & 15) * 4;
            *(float4*)(sK + row*68 + col) = *(const float4*)(Kg + (size_t)(kb*128 + row)*64 + col);
            // V: sigma-permute k-row within its 8-group
            const int u = row & 7;
            const int rowp = (row & ~7) | ((u & 1) ? (4 + (u >> 1)) : (u >> 1));
            *(float4*)(sV + rowp*72 + col) = *(const float4*)(Vg + (size_t)(kb*128 + row)*64 + col);
        }
        __syncthreads();

        #pragma unroll
        for (int ntc = 0; ntc < 2; ntc++){
            float s[8][4];
            #pragma unroll
            for (int i = 0; i < 8; i++){ s[i][0]=s[i][1]=s[i][2]=s[i][3]=0.f; }
            #pragma unroll
            for (int ks = 0; ks < 8; ks++){
                #pragma unroll
                for (int nt = 0; nt < 8; nt++){
                    uint32_t bf[2];
                    const float* p = sK + ((ntc*8 + nt)*8 + r)*68 + ks*8 + c;
                    bf[0] = __float_as_uint(p[0]);
                    bf[1] = __float_as_uint(p[4]);
                    mma8(s[nt], aq[ks], bf);
                }
            }
            #pragma unroll
            for (int nt = 0; nt < 8; nt++){
                const int g = ntc*8 + nt;               // S col-group == PV k-group
                const float p0 = exp2f(s[nt][0]*CF) * inv0;
                const float p1 = exp2f(s[nt][1]*CF) * inv0;
                const float p2 = exp2f(s[nt][2]*CF) * inv1;
                const float p3 = exp2f(s[nt][3]*CF) * inv1;
                // direct att store (one 32B sector per row per group)
                const int colb = kb*128 + g*8 + 2*c;
                *(float2*)(att0 + colb) = make_float2(p0, p1);
                *(float2*)(att1 + colb) = make_float2(p2, p3);
                // P as A-fragment (C->A identity under sigma-permuted V)
                uint32_t ap[4];
                ap[0] = __float_as_uint(p0);
                ap[1] = __float_as_uint(p2);
                ap[2] = __float_as_uint(p1);
                ap[3] = __float_as_uint(p3);
                #pragma unroll
                for (int ntv = 0; ntv < 8; ntv++){
                    uint32_t bv[2];
                    const float* q2 = sV + (g*8 + c)*72 + ntv*8 + r;
                    bv[0] = __float_as_uint(q2[0]);
                    bv[1] = __float_as_uint(q2[4*72]);
                    mma8(yv[ntv], ap, bv);
                }
            }
        }
    }

    // write Y to g_y in [B,T,D] layout, tf32-rounded (== oproj staging cvt)
    #pragma unroll
    for (int nt = 0; nt < 8; nt++){
        const int row = qb*128 + warp*16 + r;
        const int col = h*64 + nt*8 + 2*c;
        *(float2*)(g_y + ((size_t)b*TT + row)*DD + col)     = make_float2(f2tff(yv[nt][0]), f2tff(yv[nt][1]));
        *(float2*)(g_y + ((size_t)b*TT + row + 8)*DD + col) = make_float2(f2tff(yv[nt][2]), f2tff(yv[nt][3]));
    }
}

// ---------------------------------------------------------------------------
// K3: output projection + bias.  grid (32, 8), 256 thr, 2 CTAs/SM.
// ---------------------------------------------------------------------------
extern "C" __global__ void __launch_bounds__(256, 2)
oproj_kernel(const float* __restrict__ bo, float* __restrict__ out)
{
    extern __shared__ float smg[];
    const int m0 = blockIdx.x * 128, n0 = blockIdx.y * 128;

    float acc[16][4];
    gemm_128_128_async(g_y, g_wc + (size_t)3*DD*DD, m0, n0, acc, smg);

    const int lane = threadIdx.x & 31, warp = threadIdx.x >> 5;
    const int wm = (warp >> 2) * 64, wn = (warp & 3) * 32;
    const int r = lane >> 2, c = lane & 3;
    #pragma unroll
    for (int mt = 0; mt < 4; mt++){
        #pragma unroll
        for (int nt = 0; nt < 4; nt++){
            const float* f = acc[mt*4 + nt];
            const int m_ = m0 + wm + mt*16 + r;
            const int n_ = n0 + wn + nt*8 + c*2;
            const float2 bias = *(const float2*)(bo + n_);
            float2 v0 = make_float2(f[0] + bias.x, f[1] + bias.y);
            float2 v1 = make_float2(f[2] + bias.x, f[3] + bias.y);
            *(float2*)(out + (size_t)m_*DD + n_)       = v0;
            *(float2*)(out + (size_t)(m_ + 8)*DD + n_) = v1;
        }
    }
}

// ---------------------------------------------------------------------------
extern "C" void kernel_launch(void* const* d_in, const int* in_sizes, int n_in,
                              void* d_out, int out_size)
{
    (void)in_sizes; (void)n_in; (void)out_size;
    const float* x  = (const float*)d_in[0];
    const float* Wq = (const float*)d_in[1];
    const float* Wk = (const float*)d_in[2];
    const float* Wv = (const float*)d_in[3];
    const float* Wo = (const float*)d_in[4];
    const float* bo = (const float*)d_in[5];

    float* y_out = (float*)d_out;                       // [B,T,D]
    float* att   = y_out + (size_t)BT * DD;             // [B,H,T,T]

    const int gemm_smem = 18432 * 4;    // 73728 B (double-buffered A+B)
    const int attn_smem = (128*68 + 128*68 + 128*72 + 128) * 4;   // 107008 B
    cudaFuncSetAttribute(qkv_kernel,   cudaFuncAttributeMaxDynamicSharedMemorySize, gemm_smem);
    cudaFuncSetAttribute(oproj_kernel, cudaFuncAttributeMaxDynamicSharedMemorySize, gemm_smem);
    cudaFuncSetAttribute(attn_kernel,  cudaFuncAttributeMaxDynamicSharedMemorySize, attn_smem);

    conv_kernel<<<dim3(256, 5), 256>>>(x, Wq, Wk, Wv, Wo);
    qkv_kernel<<<dim3(32, 8, 3), 256, gemm_smem>>>();
    attn_kernel<<<dim3(16, 16, 2), 256, attn_smem>>>(att);
    oproj_kernel<<<dim3(32, 8), 256, gemm_smem>>>(bo, y_out);
}

// round 13
// speedup vs baseline: 1.3322x; 1.0106x over previous
#include <cuda_runtime.h>
#include <cstdint>
#include <cstddef>

#define BB 2
#define TT 2048
#define DD 1024
#define HH 16
#define HS 64
#define BT (BB*TT)

// Scratch (allocation-free rule: __device__ globals)
__device__ float g_q[BB*HH*TT*HS];
__device__ float g_k[BB*HH*TT*HS];
__device__ float g_v[BB*HH*TT*HS];
__device__ float g_y[BT*DD];         // tf32-rounded by attn epilogue
__device__ float g_xc[BT*DD];        // tf32-rounded x
__device__ float g_wc[4*DD*DD];      // tf32-rounded Wq,Wk,Wv,Wo

__device__ __forceinline__ uint32_t f2tf(float x){
    uint32_t r; asm("cvt.rna.tf32.f32 %0, %1;" : "=r"(r) : "f"(x)); return r;
}
__device__ __forceinline__ float f2tff(float x){ return __uint_as_float(f2tf(x)); }

__device__ __forceinline__ void mma8(float* c, const uint32_t* a, const uint32_t* b){
    asm volatile(
        "mma.sync.aligned.m16n8k8.row.col.f32.tf32.tf32.f32 "
        "{%0,%1,%2,%3}, {%4,%5,%6,%7}, {%8,%9}, {%0,%1,%2,%3};\n"
        : "+f"(c[0]), "+f"(c[1]), "+f"(c[2]), "+f"(c[3])
        : "r"(a[0]), "r"(a[1]), "r"(a[2]), "r"(a[3]), "r"(b[0]), "r"(b[1]));
}

__device__ __forceinline__ void cpa16(float* dst_smem, const float* src){
    uint32_t d = (uint32_t)__cvta_generic_to_shared(dst_smem);
    asm volatile("cp.async.cg.shared.global [%0], [%1], 16;\n" :: "r"(d), "l"(src));
}
#define CPA_COMMIT() asm volatile("cp.async.commit_group;\n" ::: "memory")
#define CPA_WAIT0()  asm volatile("cp.async.wait_group 0;\n" ::: "memory")

// ---------------------------------------------------------------------------
// conv: tf32-round x and the 4 weights once.  grid (256, 5), 256 thr.
// ---------------------------------------------------------------------------
extern "C" __global__ void __launch_bounds__(256)
conv_kernel(const float* __restrict__ x,  const float* __restrict__ Wq,
            const float* __restrict__ Wk, const float* __restrict__ Wv,
            const float* __restrict__ Wo)
{
    const float4* src; float4* dst; int n4;
    switch (blockIdx.y){
        case 0:  src = (const float4*)x;  dst = (float4*)g_xc;             n4 = BT*DD/4; break;
        case 1:  src = (const float4*)Wq; dst = (float4*)(g_wc);           n4 = DD*DD/4; break;
        case 2:  src = (const float4*)Wk; dst = (float4*)(g_wc + DD*DD);   n4 = DD*DD/4; break;
        case 3:  src = (const float4*)Wv; dst = (float4*)(g_wc + 2*DD*DD); n4 = DD*DD/4; break;
        default: src = (const float4*)Wo; dst = (float4*)(g_wc + 3*DD*DD); n4 = DD*DD/4; break;
    }
    for (int i = blockIdx.x*blockDim.x + threadIdx.x; i < n4; i += gridDim.x*blockDim.x){
        float4 v = src[i];
        v.x = f2tff(v.x); v.y = f2tff(v.y); v.z = f2tff(v.z); v.w = f2tff(v.w);
        dst[i] = v;
    }
}

// ---------------------------------------------------------------------------
// 128x128 tile GEMM (R12 committed version: cp.async, zero cvt, 2 CTAs/SM).
// ---------------------------------------------------------------------------
__device__ __forceinline__ void gemm_128_128_async(
    const float* __restrict__ A, const float* __restrict__ W,
    int m0, int n0, float acc[16][4], float* sm)
{
    float* sAb[2] = { sm,          sm + 4608 };
    float* sBb[2] = { sm + 9216,   sm + 13824 };

    const int t = threadIdx.x, lane = t & 31, warp = t >> 5;
    const int wm = (warp >> 2) * 64, wn = (warp & 3) * 32;
    const int r = lane >> 2, c = lane & 3;
    const int lrow = t >> 3, lc4 = (t & 7) * 4;

    #pragma unroll
    for (int i = 0; i < 16; i++){ acc[i][0]=acc[i][1]=acc[i][2]=acc[i][3]=0.f; }

    #pragma unroll
    for (int i = 0; i < 4; i++){
        cpa16(sAb[0] + (lrow + 32*i)*36 + lc4, A + (size_t)(m0 + lrow + 32*i)*DD + lc4);
        cpa16(sBb[0] + (lrow + 32*i)*36 + lc4, W + (size_t)(n0 + lrow + 32*i)*DD + lc4);
    }
    CPA_COMMIT();

    for (int ch = 0; ch < 32; ch++){
        CPA_WAIT0();
        __syncthreads();
        if (ch < 31){
            const int k0 = (ch + 1) * 32;
            float* dA = sAb[(ch + 1) & 1];
            float* dB = sBb[(ch + 1) & 1];
            #pragma unroll
            for (int i = 0; i < 4; i++){
                cpa16(dA + (lrow + 32*i)*36 + lc4, A + (size_t)(m0 + lrow + 32*i)*DD + k0 + lc4);
                cpa16(dB + (lrow + 32*i)*36 + lc4, W + (size_t)(n0 + lrow + 32*i)*DD + k0 + lc4);
            }
            CPA_COMMIT();
        }
        const float* sA = sAb[ch & 1];
        const float* sB = sBb[ch & 1];
        #pragma unroll
        for (int ks = 0; ks < 4; ks++){
            uint32_t af[4][4], bf[4][2];
            #pragma unroll
            for (int mt = 0; mt < 4; mt++){
                const float* p = sA + (wm + mt*16 + r)*36 + ks*8 + c;
                af[mt][0] = __float_as_uint(p[0]);
                af[mt][1] = __float_as_uint(p[8*36]);
                af[mt][2] = __float_as_uint(p[4]);
                af[mt][3] = __float_as_uint(p[8*36 + 4]);
            }
            #pragma unroll
            for (int nt = 0; nt < 4; nt++){
                const float* p = sB + (wn + nt*8 + r)*36 + ks*8 + c;
                bf[nt][0] = __float_as_uint(p[0]);
                bf[nt][1] = __float_as_uint(p[4]);
            }
            #pragma unroll
            for (int mt = 0; mt < 4; mt++)
                #pragma unroll
                for (int nt = 0; nt < 4; nt++)
                    mma8(acc[mt*4 + nt], af[mt], bf[nt]);
        }
    }
}

// ---------------------------------------------------------------------------
// K1: QKV projection.  grid (32, 8, 3), 256 thr, 2 CTAs/SM.
// ---------------------------------------------------------------------------
extern "C" __global__ void __launch_bounds__(256, 2)
qkv_kernel()
{
    extern __shared__ float smg[];
    const int sel = blockIdx.z;
    const float* W = g_wc + (size_t)sel * DD * DD;
    float* dst     = (sel == 0) ? g_q : ((sel == 1) ? g_k : g_v);
    const int m0 = blockIdx.x * 128, n0 = blockIdx.y * 128;

    float acc[16][4];
    gemm_128_128_async(g_xc, W, m0, n0, acc, smg);

    const int lane = threadIdx.x & 31, warp = threadIdx.x >> 5;
    const int wm = (warp >> 2) * 64, wn = (warp & 3) * 32;
    const int r = lane >> 2, c = lane & 3;
    #pragma unroll
    for (int mt = 0; mt < 4; mt++){
        #pragma unroll
        for (int nt = 0; nt < 4; nt++){
            const float* f = acc[mt*4 + nt];
            const int m_ = m0 + wm + mt*16 + r;
            const int n_ = n0 + wn + nt*8 + c*2;
            const int b  = m_ >> 11, h = n_ >> 6, hs = n_ & 63;
            const int t0 = m_ & 2047, t1 = (m_ + 8) & 2047;
            float2 v0 = make_float2(f2tff(f[0]), f2tff(f[1]));
            float2 v1 = make_float2(f2tff(f[2]), f2tff(f[3]));
            *(float2*)(dst + ((size_t)((b<<4) + h)*TT + t0)*HS + hs) = v0;
            *(float2*)(dst + ((size_t)((b<<4) + h)*TT + t1)*HS + hs) = v1;
        }
    }
}

// ---------------------------------------------------------------------------
// K2: fused attention v3.  grid (16, 16, 2), 256 thr, 2 CTAs/SM.
// PASS 1 retiled to warp = 32(q) x 64(keys): each K-fragment feeds 2 m-frags,
// halving the redundant K-fragment LDS stream (the pass-1 crossbar binder).
// Row-sums combined from the two key-half partials via sL2[2][128].
// PASS 2 identical to the R11/R12 winner (direct att store + register-P PV).
// ---------------------------------------------------------------------------
extern "C" __global__ void __launch_bounds__(256, 2)
attn_kernel(float* __restrict__ att)
{
    extern __shared__ float sm[];
    float* sQ  = sm;                   // 128 x 68
    float* sK  = sQ + 128*68;          // 128 x 68
    float* sV  = sK + 128*68;          // 128 x 72 (k-rows sigma-permuted)
    float* sL0 = sV + 128*72;          // 128 row sums, key half 0
    float* sL1 = sL0 + 128;            // 128 row sums, key half 1

    const int t = threadIdx.x, lane = t & 31, warp = t >> 5;
    const int r = lane >> 2, c = lane & 3;
    const int qb = blockIdx.x, h = blockIdx.y, b = blockIdx.z;

    const size_t headoff = (size_t)(b*HH + h) * TT * HS;
    const float* Qg = g_q + headoff + (size_t)qb * 128 * HS;
    const float* Kg = g_k + headoff;
    const float* Vg = g_v + headoff;
    float* attg = att + ((size_t)(b*HH + h)*TT + (size_t)qb*128) * TT;

    // load Q tile
    #pragma unroll
    for (int i = 0; i < 8; i++){
        const int idx = t + 256*i, row = idx >> 4, col = (idx & 15) * 4;
        *(float4*)(sQ + row*68 + col) = *(const float4*)(Qg + row*64 + col);
    }
    __syncthreads();

    const float CF = 0.18033688011112042f;   // log2(e) / sqrt(64)

    // ================= PASS 1: warp tile 32 x 64 =================
    {
        const int wm2 = (warp >> 1) * 32;     // q-row base (0/32/64/96)
        const int kb0 = (warp & 1) * 64;      // key half offset
        float* sLh = (warp & 1) ? sL1 : sL0;

        // Q fragments for 2 m-groups (held in regs for all of pass 1)
        uint32_t aq2[8][2][4];
        #pragma unroll
        for (int ks = 0; ks < 8; ks++){
            #pragma unroll
            for (int mf = 0; mf < 2; mf++){
                const float* p = sQ + (wm2 + mf*16 + r)*68 + ks*8 + c;
                aq2[ks][mf][0] = __float_as_uint(p[0]);
                aq2[ks][mf][1] = __float_as_uint(p[8*68]);
                aq2[ks][mf][2] = __float_as_uint(p[4]);
                aq2[ks][mf][3] = __float_as_uint(p[8*68 + 4]);
            }
        }

        float lp[2][2];
        lp[0][0]=lp[0][1]=lp[1][0]=lp[1][1]=0.f;

        for (int kb = 0; kb < 16; kb++){
            __syncthreads();
            #pragma unroll
            for (int i = 0; i < 8; i++){
                const int idx = t + 256*i, row = idx >> 4, col = (idx & 15) * 4;
                *(float4*)(sK + row*68 + col) = *(const float4*)(Kg + (size_t)(kb*128 + row)*64 + col);
            }
            __syncthreads();

            #pragma unroll
            for (int ntc = 0; ntc < 2; ntc++){
                float s[2][4][4];
                #pragma unroll
                for (int mf = 0; mf < 2; mf++)
                    #pragma unroll
                    for (int i = 0; i < 4; i++){ s[mf][i][0]=s[mf][i][1]=s[mf][i][2]=s[mf][i][3]=0.f; }
                #pragma unroll
                for (int ks = 0; ks < 8; ks++){
                    #pragma unroll
                    for (int nt = 0; nt < 4; nt++){
                        uint32_t bf[2];
                        const float* p = sK + (kb0 + (ntc*4 + nt)*8 + r)*68 + ks*8 + c;
                        bf[0] = __float_as_uint(p[0]);
                        bf[1] = __float_as_uint(p[4]);
                        mma8(s[0][nt], aq2[ks][0], bf);     // K-frag reused by both m-groups
                        mma8(s[1][nt], aq2[ks][1], bf);
                    }
                }
                #pragma unroll
                for (int mf = 0; mf < 2; mf++)
                    #pragma unroll
                    for (int nt = 0; nt < 4; nt++){
                        lp[mf][0] += exp2f(s[mf][nt][0]*CF) + exp2f(s[mf][nt][1]*CF);
                        lp[mf][1] += exp2f(s[mf][nt][2]*CF) + exp2f(s[mf][nt][3]*CF);
                    }
            }
        }
        // reduce over c lanes, publish per-half row sums
        #pragma unroll
        for (int mf = 0; mf < 2; mf++){
            #pragma unroll
            for (int j = 0; j < 2; j++){
                lp[mf][j] += __shfl_xor_sync(0xffffffffu, lp[mf][j], 1);
                lp[mf][j] += __shfl_xor_sync(0xffffffffu, lp[mf][j], 2);
            }
        }
        __syncthreads();
        if (c == 0){
            sLh[wm2 + r]      = lp[0][0];
            sLh[wm2 + r + 8]  = lp[0][1];
            sLh[wm2 + 16 + r]     = lp[1][0];
            sLh[wm2 + 16 + r + 8] = lp[1][1];
        }
        __syncthreads();
    }

    const int qrow = warp*16 + r;
    const float inv0 = 1.0f / (sL0[qrow]     + sL1[qrow]);
    const float inv1 = 1.0f / (sL0[qrow + 8] + sL1[qrow + 8]);

    // preload pass-2 Q fragments (R11 mapping: warp = 16 q-rows x 128 keys)
    uint32_t aq[8][4];
    #pragma unroll
    for (int ks = 0; ks < 8; ks++){
        const float* p = sQ + (warp*16 + r)*68 + ks*8 + c;
        aq[ks][0] = __float_as_uint(p[0]);
        aq[ks][1] = __float_as_uint(p[8*68]);
        aq[ks][2] = __float_as_uint(p[4]);
        aq[ks][3] = __float_as_uint(p[8*68 + 4]);
    }

    // ================= PASS 2 (unchanged R11/R12 winner) =================
    float yv[8][4];
    #pragma unroll
    for (int i = 0; i < 8; i++){ yv[i][0]=yv[i][1]=yv[i][2]=yv[i][3]=0.f; }

    float* att0 = attg + (size_t)qrow * TT;
    float* att1 = attg + (size_t)(qrow + 8) * TT;

    for (int kb = 0; kb < 16; kb++){
        __syncthreads();
        #pragma unroll
        for (int i = 0; i < 8; i++){
            const int idx = t + 256*i, row = idx >> 4, col = (idx & 15) * 4;
            *(float4*)(sK + row*68 + col) = *(const float4*)(Kg + (size_t)(kb*128 + row)*64 + col);
            const int u = row & 7;
            const int rowp = (row & ~7) | ((u & 1) ? (4 + (u >> 1)) : (u >> 1));
            *(float4*)(sV + rowp*72 + col) = *(const float4*)(Vg + (size_t)(kb*128 + row)*64 + col);
        }
        __syncthreads();

        #pragma unroll
        for (int ntc = 0; ntc < 2; ntc++){
            float s[8][4];
            #pragma unroll
            for (int i = 0; i < 8; i++){ s[i][0]=s[i][1]=s[i][2]=s[i][3]=0.f; }
            #pragma unroll
            for (int ks = 0; ks < 8; ks++){
                #pragma unroll
                for (int nt = 0; nt < 8; nt++){
                    uint32_t bf[2];
                    const float* p = sK + ((ntc*8 + nt)*8 + r)*68 + ks*8 + c;
                    bf[0] = __float_as_uint(p[0]);
                    bf[1] = __float_as_uint(p[4]);
                    mma8(s[nt], aq[ks], bf);
                }
            }
            #pragma unroll
            for (int nt = 0; nt < 8; nt++){
                const int g = ntc*8 + nt;
                const float p0 = exp2f(s[nt][0]*CF) * inv0;
                const float p1 = exp2f(s[nt][1]*CF) * inv0;
                const float p2 = exp2f(s[nt][2]*CF) * inv1;
                const float p3 = exp2f(s[nt][3]*CF) * inv1;
                const int colb = kb*128 + g*8 + 2*c;
                *(float2*)(att0 + colb) = make_float2(p0, p1);
                *(float2*)(att1 + colb) = make_float2(p2, p3);
                uint32_t ap[4];
                ap[0] = __float_as_uint(p0);
                ap[1] = __float_as_uint(p2);
                ap[2] = __float_as_uint(p1);
                ap[3] = __float_as_uint(p3);
                #pragma unroll
                for (int ntv = 0; ntv < 8; ntv++){
                    uint32_t bv[2];
                    const float* q2 = sV + (g*8 + c)*72 + ntv*8 + r;
                    bv[0] = __float_as_uint(q2[0]);
                    bv[1] = __float_as_uint(q2[4*72]);
                    mma8(yv[ntv], ap, bv);
                }
            }
        }
    }

    // write Y (tf32-rounded) to g_y in [B,T,D] layout
    #pragma unroll
    for (int nt = 0; nt < 8; nt++){
        const int row = qb*128 + warp*16 + r;
        const int col = h*64 + nt*8 + 2*c;
        *(float2*)(g_y + ((size_t)b*TT + row)*DD + col)     = make_float2(f2tff(yv[nt][0]), f2tff(yv[nt][1]));
        *(float2*)(g_y + ((size_t)b*TT + row + 8)*DD + col) = make_float2(f2tff(yv[nt][2]), f2tff(yv[nt][3]));
    }
}

// ---------------------------------------------------------------------------
// K3: output projection + bias.  grid (32, 8), 256 thr, 2 CTAs/SM.
// ---------------------------------------------------------------------------
extern "C" __global__ void __launch_bounds__(256, 2)
oproj_kernel(const float* __restrict__ bo, float* __restrict__ out)
{
    extern __shared__ float smg[];
    const int m0 = blockIdx.x * 128, n0 = blockIdx.y * 128;

    float acc[16][4];
    gemm_128_128_async(g_y, g_wc + (size_t)3*DD*DD, m0, n0, acc, smg);

    const int lane = threadIdx.x & 31, warp = threadIdx.x >> 5;
    const int wm = (warp >> 2) * 64, wn = (warp & 3) * 32;
    const int r = lane >> 2, c = lane & 3;
    #pragma unroll
    for (int mt = 0; mt < 4; mt++){
        #pragma unroll
        for (int nt = 0; nt < 4; nt++){
            const float* f = acc[mt*4 + nt];
            const int m_ = m0 + wm + mt*16 + r;
            const int n_ = n0 + wn + nt*8 + c*2;
            const float2 bias = *(const float2*)(bo + n_);
            float2 v0 = make_float2(f[0] + bias.x, f[1] + bias.y);
            float2 v1 = make_float2(f[2] + bias.x, f[3] + bias.y);
            *(float2*)(out + (size_t)m_*DD + n_)       = v0;
            *(float2*)(out + (size_t)(m_ + 8)*DD + n_) = v1;
        }
    }
}

// ---------------------------------------------------------------------------
extern "C" void kernel_launch(void* const* d_in, const int* in_sizes, int n_in,
                              void* d_out, int out_size)
{
    (void)in_sizes; (void)n_in; (void)out_size;
    const float* x  = (const float*)d_in[0];
    const float* Wq = (const float*)d_in[1];
    const float* Wk = (const float*)d_in[2];
    const float* Wv = (const float*)d_in[3];
    const float* Wo = (const float*)d_in[4];
    const float* bo = (const float*)d_in[5];

    float* y_out = (float*)d_out;                       // [B,T,D]
    float* att   = y_out + (size_t)BT * DD;             // [B,H,T,T]

    const int gemm_smem = 18432 * 4;    // 73728 B
    const int attn_smem = (128*68 + 128*68 + 128*72 + 256) * 4;   // 107520 B
    cudaFuncSetAttribute(qkv_kernel,   cudaFuncAttributeMaxDynamicSharedMemorySize, gemm_smem);
    cudaFuncSetAttribute(oproj_kernel, cudaFuncAttributeMaxDynamicSharedMemorySize, gemm_smem);
    cudaFuncSetAttribute(attn_kernel,  cudaFuncAttributeMaxDynamicSharedMemorySize, attn_smem);

    conv_kernel<<<dim3(256, 5), 256>>>(x, Wq, Wk, Wv, Wo);
    qkv_kernel<<<dim3(32, 8, 3), 256, gemm_smem>>>();
    attn_kernel<<<dim3(16, 16, 2), 256, attn_smem>>>(att);
    oproj_kernel<<<dim3(32, 8), 256, gemm_smem>>>(bo, y_out);
}

// round 14
// speedup vs baseline: 2.3245x; 1.7449x over previous
#include <cuda_runtime.h>
#include <cuda_fp16.h>
#include <cstdint>
#include <cstddef>

#define BB 2
#define TT 2048
#define DD 1024
#define HH 16
#define HS 64
#define BT (BB*TT)

// Scratch (allocation-free rule: __device__ globals)
__device__ __half g_q[BB*HH*TT*HS];     // [b,h,t,hs]
__device__ __half g_k[BB*HH*TT*HS];     // [b,h,t,hs]
__device__ __half g_vt[BB*HH*HS*TT];    // [b,h,hs,t]  (transposed for PV B-frags)
__device__ __half g_yh[BT*DD];          // attn output, fp16
__device__ __half g_xh[BT*DD];          // fp16 x
__device__ __half g_wh[4*DD*DD];        // fp16 Wq,Wk,Wv,Wo

__device__ __forceinline__ void mma16(float* c, const uint32_t* a, const uint32_t* b){
    asm volatile(
        "mma.sync.aligned.m16n8k16.row.col.f32.f16.f16.f32 "
        "{%0,%1,%2,%3}, {%4,%5,%6,%7}, {%8,%9}, {%0,%1,%2,%3};\n"
        : "+f"(c[0]), "+f"(c[1]), "+f"(c[2]), "+f"(c[3])
        : "r"(a[0]), "r"(a[1]), "r"(a[2]), "r"(a[3]), "r"(b[0]), "r"(b[1]));
}

__device__ __forceinline__ void cpa16(__half* dst_smem, const __half* src){
    uint32_t d = (uint32_t)__cvta_generic_to_shared(dst_smem);
    asm volatile("cp.async.cg.shared.global [%0], [%1], 16;\n" :: "r"(d), "l"(src));
}
#define CPA_COMMIT() asm volatile("cp.async.commit_group;\n" ::: "memory")
#define CPA_WAIT0()  asm volatile("cp.async.wait_group 0;\n" ::: "memory")

__device__ __forceinline__ uint32_t h2u(__half2 h){ return *reinterpret_cast<uint32_t*>(&h); }

// ---------------------------------------------------------------------------
// conv: round x and the 4 weights to fp16 once.  grid (256, 5), 256 thr.
// ---------------------------------------------------------------------------
extern "C" __global__ void __launch_bounds__(256)
conv_kernel(const float* __restrict__ x,  const float* __restrict__ Wq,
            const float* __restrict__ Wk, const float* __restrict__ Wv,
            const float* __restrict__ Wo)
{
    const float4* src; __half* dst; int n4;
    switch (blockIdx.y){
        case 0:  src = (const float4*)x;  dst = g_xh;            n4 = BT*DD/4; break;
        case 1:  src = (const float4*)Wq; dst = g_wh;            n4 = DD*DD/4; break;
        case 2:  src = (const float4*)Wk; dst = g_wh + DD*DD;    n4 = DD*DD/4; break;
        case 3:  src = (const float4*)Wv; dst = g_wh + 2*DD*DD;  n4 = DD*DD/4; break;
        default: src = (const float4*)Wo; dst = g_wh + 3*DD*DD;  n4 = DD*DD/4; break;
    }
    for (int i = blockIdx.x*blockDim.x + threadIdx.x; i < n4; i += gridDim.x*blockDim.x){
        float4 v = src[i];
        __half2* d = (__half2*)(dst + (size_t)i*4);
        d[0] = __floats2half2_rn(v.x, v.y);
        d[1] = __floats2half2_rn(v.z, v.w);
    }
}

// ---------------------------------------------------------------------------
// fp16 GEMM: 128x128 tile of A(MxK rm) * W^T (W NxK rm), K = 1024.
// k-chunk 64 halfs, double-buffered cp.async, one barrier per chunk.
// 256 thr, 8 warps, warp tile 64x32; m16n8k16.  smem rows 72 halfs (pad 8).
// ---------------------------------------------------------------------------
__device__ __forceinline__ void gemm_fp16_async(
    const __half* __restrict__ A, const __half* __restrict__ W,
    int m0, int n0, float acc[16][4], __half* sm)
{
    __half* sAb[2] = { sm,           sm + 9216 };
    __half* sBb[2] = { sm + 18432,   sm + 27648 };

    const int t = threadIdx.x, lane = t & 31, warp = t >> 5;
    const int wm = (warp >> 2) * 64, wn = (warp & 3) * 32;
    const int r = lane >> 2, c = lane & 3;

    #pragma unroll
    for (int i = 0; i < 16; i++){ acc[i][0]=acc[i][1]=acc[i][2]=acc[i][3]=0.f; }

    // prefetch chunk 0 (128 rows x 64 halfs per operand)
    #pragma unroll
    for (int i = 0; i < 4; i++){
        const int idx = t + 256*i, row = idx >> 3, seg = idx & 7;
        cpa16(sAb[0] + row*72 + seg*8, A + (size_t)(m0 + row)*DD + seg*8);
        cpa16(sBb[0] + row*72 + seg*8, W + (size_t)(n0 + row)*DD + seg*8);
    }
    CPA_COMMIT();

    for (int ch = 0; ch < 16; ch++){
        CPA_WAIT0();
        __syncthreads();
        if (ch < 15){
            const int k0 = (ch + 1) * 64;
            __half* dA = sAb[(ch + 1) & 1];
            __half* dB = sBb[(ch + 1) & 1];
            #pragma unroll
            for (int i = 0; i < 4; i++){
                const int idx = t + 256*i, row = idx >> 3, seg = idx & 7;
                cpa16(dA + row*72 + seg*8, A + (size_t)(m0 + row)*DD + k0 + seg*8);
                cpa16(dB + row*72 + seg*8, W + (size_t)(n0 + row)*DD + k0 + seg*8);
            }
            CPA_COMMIT();
        }
        const __half* sA = sAb[ch & 1];
        const __half* sB = sBb[ch & 1];
        #pragma unroll
        for (int ks = 0; ks < 4; ks++){
            uint32_t af[4][4], bf[4][2];
            #pragma unroll
            for (int mt = 0; mt < 4; mt++){
                const __half* p = sA + (wm + mt*16 + r)*72 + ks*16 + c*2;
                af[mt][0] = *(const uint32_t*)(p);
                af[mt][1] = *(const uint32_t*)(p + 8*72);
                af[mt][2] = *(const uint32_t*)(p + 8);
                af[mt][3] = *(const uint32_t*)(p + 8*72 + 8);
            }
            #pragma unroll
            for (int nt = 0; nt < 4; nt++){
                const __half* p = sB + (wn + nt*8 + r)*72 + ks*16 + c*2;
                bf[nt][0] = *(const uint32_t*)(p);
                bf[nt][1] = *(const uint32_t*)(p + 8);
            }
            #pragma unroll
            for (int mt = 0; mt < 4; mt++)
                #pragma unroll
                for (int nt = 0; nt < 4; nt++)
                    mma16(acc[mt*4 + nt], af[mt], bf[nt]);
        }
    }
}

// ---------------------------------------------------------------------------
// K1: QKV projection.  grid (32, 8, 3), 256 thr, 2 CTAs/SM.
// q,k stored [b,h,t,hs]; v stored TRANSPOSED [b,h,hs,t].
// ---------------------------------------------------------------------------
extern "C" __global__ void __launch_bounds__(256, 2)
qkv_kernel()
{
    extern __shared__ __half smh[];
    const int sel = blockIdx.z;
    const __half* W = g_wh + (size_t)sel * DD * DD;
    const int m0 = blockIdx.x * 128, n0 = blockIdx.y * 128;

    float acc[16][4];
    gemm_fp16_async(g_xh, W, m0, n0, acc, smh);

    const int lane = threadIdx.x & 31, warp = threadIdx.x >> 5;
    const int wm = (warp >> 2) * 64, wn = (warp & 3) * 32;
    const int r = lane >> 2, c = lane & 3;
    #pragma unroll
    for (int mt = 0; mt < 4; mt++){
        #pragma unroll
        for (int nt = 0; nt < 4; nt++){
            const float* f = acc[mt*4 + nt];
            const int m_ = m0 + wm + mt*16 + r;
            const int n_ = n0 + wn + nt*8 + c*2;
            const int b  = m_ >> 11, h = n_ >> 6, hs = n_ & 63;
            const int t0 = m_ & 2047, t1 = (m_ + 8) & 2047;
            if (sel == 2){
                __half* vt = g_vt + (size_t)((b<<4) + h)*HS*TT;
                vt[(size_t)hs*TT + t0]     = __float2half_rn(f[0]);
                vt[(size_t)(hs+1)*TT + t0] = __float2half_rn(f[1]);
                vt[(size_t)hs*TT + t1]     = __float2half_rn(f[2]);
                vt[(size_t)(hs+1)*TT + t1] = __float2half_rn(f[3]);
            } else {
                __half* dst = (sel == 0) ? g_q : g_k;
                __half* base = dst + ((size_t)((b<<4) + h)*TT)*HS + hs;
                *(__half2*)(base + (size_t)t0*HS) = __floats2half2_rn(f[0], f[1]);
                *(__half2*)(base + (size_t)t1*HS) = __floats2half2_rn(f[2], f[3]);
            }
        }
    }
}

// ---------------------------------------------------------------------------
// K2: fused attention, fp16 MMA.  grid (16, 16, 2), 256 thr, 2 CTAs/SM.
// Warp = 16 q-rows x 128 keys, m16n8k16 (4 k-steps over HS=64).
// Pass 1: row sums of exp(s) (no max needed: |s| <= ~3.3).
// Pass 2: direct att store from C-frags + register-P PV (P packed to half2;
//         fp16 k16 A-frag slots match QK C-frag cols natively, V transposed).
// smem: sQ 128x72h, sK 128x72h, sVt 64x136h, sL 128f  = 54784 B.
// ---------------------------------------------------------------------------
extern "C" __global__ void __launch_bounds__(256, 2)
attn_kernel(float* __restrict__ att)
{
    extern __shared__ __half smh[];
    __half* sQ  = smh;                  // 128 x 72
    __half* sK  = sQ + 128*72;          // 128 x 72
    __half* sVt = sK + 128*72;          // 64 x 136  (rows = hs, cols = keys)
    float*  sL  = (float*)(sVt + 64*136);

    const int t = threadIdx.x, lane = t & 31, warp = t >> 5;
    const int r = lane >> 2, c = lane & 3;
    const int qb = blockIdx.x, h = blockIdx.y, b = blockIdx.z;

    const size_t headoff = (size_t)(b*HH + h) * TT * HS;
    const __half* Qg  = g_q + headoff + (size_t)qb * 128 * HS;
    const __half* Kg  = g_k + headoff;
    const __half* Vtg = g_vt + (size_t)(b*HH + h) * HS * TT;
    float* attg = att + ((size_t)(b*HH + h)*TT + (size_t)qb*128) * TT;

    // load Q tile (128 rows x 64 halfs)
    #pragma unroll
    for (int i = 0; i < 4; i++){
        const int idx = t + 256*i, row = idx >> 3, seg = idx & 7;
        *(uint4*)(sQ + row*72 + seg*8) = *(const uint4*)(Qg + (size_t)row*64 + seg*8);
    }
    __syncthreads();

    // Q A-fragments: 4 k-steps of 16 (HS=64)
    uint32_t aq[4][4];
    #pragma unroll
    for (int ks = 0; ks < 4; ks++){
        const __half* p = sQ + (warp*16 + r)*72 + ks*16 + c*2;
        aq[ks][0] = *(const uint32_t*)(p);
        aq[ks][1] = *(const uint32_t*)(p + 8*72);
        aq[ks][2] = *(const uint32_t*)(p + 8);
        aq[ks][3] = *(const uint32_t*)(p + 8*72 + 8);
    }

    const float CF = 0.18033688011112042f;   // log2(e) / sqrt(64)

    // ---- PASS 1: row sums of exp(s) ----
    float l0 = 0.f, l1 = 0.f;
    for (int kb = 0; kb < 16; kb++){
        __syncthreads();
        #pragma unroll
        for (int i = 0; i < 4; i++){
            const int idx = t + 256*i, row = idx >> 3, seg = idx & 7;
            *(uint4*)(sK + row*72 + seg*8) = *(const uint4*)(Kg + (size_t)(kb*128 + row)*64 + seg*8);
        }
        __syncthreads();

        #pragma unroll
        for (int ntc = 0; ntc < 2; ntc++){
            float s[8][4];
            #pragma unroll
            for (int i = 0; i < 8; i++){ s[i][0]=s[i][1]=s[i][2]=s[i][3]=0.f; }
            #pragma unroll
            for (int ks = 0; ks < 4; ks++){
                #pragma unroll
                for (int nt = 0; nt < 8; nt++){
                    uint32_t bf[2];
                    const __half* p = sK + ((ntc*8 + nt)*8 + r)*72 + ks*16 + c*2;
                    bf[0] = *(const uint32_t*)(p);
                    bf[1] = *(const uint32_t*)(p + 8);
                    mma16(s[nt], aq[ks], bf);
                }
            }
            #pragma unroll
            for (int nt = 0; nt < 8; nt++){
                l0 += exp2f(s[nt][0]*CF) + exp2f(s[nt][1]*CF);
                l1 += exp2f(s[nt][2]*CF) + exp2f(s[nt][3]*CF);
            }
        }
    }
    l0 += __shfl_xor_sync(0xffffffffu, l0, 1);
    l0 += __shfl_xor_sync(0xffffffffu, l0, 2);
    l1 += __shfl_xor_sync(0xffffffffu, l1, 1);
    l1 += __shfl_xor_sync(0xffffffffu, l1, 2);
    __syncthreads();
    if (c == 0){ sL[warp*16 + r] = l0; sL[warp*16 + r + 8] = l1; }
    __syncthreads();
    const float inv0 = 1.0f / sL[warp*16 + r];
    const float inv1 = 1.0f / sL[warp*16 + r + 8];

    // ---- PASS 2: direct att store + register-P PV ----
    float yv[8][4];
    #pragma unroll
    for (int i = 0; i < 8; i++){ yv[i][0]=yv[i][1]=yv[i][2]=yv[i][3]=0.f; }

    const int qrow = warp*16 + r;
    float* att0 = attg + (size_t)qrow * TT;
    float* att1 = attg + (size_t)(qrow + 8) * TT;

    for (int kb = 0; kb < 16; kb++){
        __syncthreads();
        #pragma unroll
        for (int i = 0; i < 4; i++){
            const int idx = t + 256*i, row = idx >> 3, seg = idx & 7;
            *(uint4*)(sK + row*72 + seg*8) = *(const uint4*)(Kg + (size_t)(kb*128 + row)*64 + seg*8);
        }
        #pragma unroll
        for (int i = 0; i < 4; i++){
            const int idx = t + 256*i, row = idx >> 4, seg = idx & 15;   // 64 x 128 halfs
            *(uint4*)(sVt + row*136 + seg*8) = *(const uint4*)(Vtg + (size_t)row*TT + kb*128 + seg*8);
        }
        __syncthreads();

        #pragma unroll
        for (int ntc = 0; ntc < 2; ntc++){
            float s[8][4];
            #pragma unroll
            for (int i = 0; i < 8; i++){ s[i][0]=s[i][1]=s[i][2]=s[i][3]=0.f; }
            #pragma unroll
            for (int ks = 0; ks < 4; ks++){
                #pragma unroll
                for (int nt = 0; nt < 8; nt++){
                    uint32_t bf[2];
                    const __half* p = sK + ((ntc*8 + nt)*8 + r)*72 + ks*16 + c*2;
                    bf[0] = *(const uint32_t*)(p);
                    bf[1] = *(const uint32_t*)(p + 8);
                    mma16(s[nt], aq[ks], bf);
                }
            }
            // 4 PV k-groups of 16 keys per chunk; each = two adjacent S n-frags
            #pragma unroll
            for (int jj = 0; jj < 4; jj++){
                float pa0 = exp2f(s[2*jj][0]*CF) * inv0;
                float pa1 = exp2f(s[2*jj][1]*CF) * inv0;
                float pa2 = exp2f(s[2*jj][2]*CF) * inv1;
                float pa3 = exp2f(s[2*jj][3]*CF) * inv1;
                float pb0 = exp2f(s[2*jj+1][0]*CF) * inv0;
                float pb1 = exp2f(s[2*jj+1][1]*CF) * inv0;
                float pb2 = exp2f(s[2*jj+1][2]*CF) * inv1;
                float pb3 = exp2f(s[2*jj+1][3]*CF) * inv1;

                const int colb = kb*128 + (ntc*8 + 2*jj)*8 + 2*c;
                *(float2*)(att0 + colb)     = make_float2(pa0, pa1);
                *(float2*)(att1 + colb)     = make_float2(pa2, pa3);
                *(float2*)(att0 + colb + 8) = make_float2(pb0, pb1);
                *(float2*)(att1 + colb + 8) = make_float2(pb2, pb3);

                uint32_t ap[4];
                ap[0] = h2u(__floats2half2_rn(pa0, pa1));
                ap[1] = h2u(__floats2half2_rn(pa2, pa3));
                ap[2] = h2u(__floats2half2_rn(pb0, pb1));
                ap[3] = h2u(__floats2half2_rn(pb2, pb3));

                const int kbase = ntc*64 + jj*16;
                #pragma unroll
                for (int nb = 0; nb < 8; nb++){
                    uint32_t bv[2];
                    const __half* q2 = sVt + (nb*8 + r)*136 + kbase + 2*c;
                    bv[0] = *(const uint32_t*)(q2);
                    bv[1] = *(const uint32_t*)(q2 + 8);
                    mma16(yv[nb], ap, bv);
                }
            }
        }
    }

    // write Y (fp16) to g_yh in [B,T,D] layout
    #pragma unroll
    for (int nb = 0; nb < 8; nb++){
        const int row = qb*128 + qrow;
        const int col = h*64 + nb*8 + 2*c;
        *(__half2*)(g_yh + ((size_t)b*TT + row)*DD + col)     = __floats2half2_rn(yv[nb][0], yv[nb][1]);
        *(__half2*)(g_yh + ((size_t)b*TT + row + 8)*DD + col) = __floats2half2_rn(yv[nb][2], yv[nb][3]);
    }
}

// ---------------------------------------------------------------------------
// K3: output projection + bias.  grid (32, 8), 256 thr, 2 CTAs/SM.
// ---------------------------------------------------------------------------
extern "C" __global__ void __launch_bounds__(256, 2)
oproj_kernel(const float* __restrict__ bo, float* __restrict__ out)
{
    extern __shared__ __half smh[];
    const int m0 = blockIdx.x * 128, n0 = blockIdx.y * 128;

    float acc[16][4];
    gemm_fp16_async(g_yh, g_wh + (size_t)3*DD*DD, m0, n0, acc, smh);

    const int lane = threadIdx.x & 31, warp = threadIdx.x >> 5;
    const int wm = (warp >> 2) * 64, wn = (warp & 3) * 32;
    const int r = lane >> 2, c = lane & 3;
    #pragma unroll
    for (int mt = 0; mt < 4; mt++){
        #pragma unroll
        for (int nt = 0; nt < 4; nt++){
            const float* f = acc[mt*4 + nt];
            const int m_ = m0 + wm + mt*16 + r;
            const int n_ = n0 + wn + nt*8 + c*2;
            const float2 bias = *(const float2*)(bo + n_);
            float2 v0 = make_float2(f[0] + bias.x, f[1] + bias.y);
            float2 v1 = make_float2(f[2] + bias.x, f[3] + bias.y);
            *(float2*)(out + (size_t)m_*DD + n_)       = v0;
            *(float2*)(out + (size_t)(m_ + 8)*DD + n_) = v1;
        }
    }
}

// ---------------------------------------------------------------------------
extern "C" void kernel_launch(void* const* d_in, const int* in_sizes, int n_in,
                              void* d_out, int out_size)
{
    (void)in_sizes; (void)n_in; (void)out_size;
    const float* x  = (const float*)d_in[0];
    const float* Wq = (const float*)d_in[1];
    const float* Wk = (const float*)d_in[2];
    const float* Wv = (const float*)d_in[3];
    const float* Wo = (const float*)d_in[4];
    const float* bo = (const float*)d_in[5];

    float* y_out = (float*)d_out;                       // [B,T,D]
    float* att   = y_out + (size_t)BT * DD;             // [B,H,T,T]

    const int gemm_smem = 4 * 9216 * 2;                 // 73728 B (2 bufs x A,B)
    const int attn_smem = (128*72 + 128*72 + 64*136) * 2 + 128*4;   // 54784 B
    cudaFuncSetAttribute(qkv_kernel,   cudaFuncAttributeMaxDynamicSharedMemorySize, gemm_smem);
    cudaFuncSetAttribute(oproj_kernel, cudaFuncAttributeMaxDynamicSharedMemorySize, gemm_smem);
    cudaFuncSetAttribute(attn_kernel,  cudaFuncAttributeMaxDynamicSharedMemorySize, attn_smem);

    conv_kernel<<<dim3(256, 5), 256>>>(x, Wq, Wk, Wv, Wo);
    qkv_kernel<<<dim3(32, 8, 3), 256, gemm_smem>>>();
    attn_kernel<<<dim3(16, 16, 2), 256, attn_smem>>>(att);
    oproj_kernel<<<dim3(32, 8), 256, gemm_smem>>>(bo, y_out);
}